// round 9
// baseline (speedup 1.0000x reference)
#include <cuda_runtime.h>
#include <math.h>

// RoPE-2D: x[B=32, S=1024, H=16, D=64] fp32, grid_sizes[B,2] int32.
// Combined rotation: rot(i*th) ∘ rot(j*th) == rot((i+j)*th).
// Best config (R7): one-shot grid, block=128, 4 float4/thread, loads
// front-batched with __ldcs (streaming, evict-first). Stores use default
// .wb policy: kernel completes when stores land in L2; dirty write-back
// overlaps the next replay instead of serializing inside the timed window.

#define F4_PER_ROW 16        // D=64 floats = 16 float4
#define S_LOG2 10

__global__ void __launch_bounds__(128) rope2d_kernel(const float4* __restrict__ x,
                                                     const int* __restrict__ grid_sizes,
                                                     float4* __restrict__ out) {
    int tid = threadIdx.x;                 // 0..127
    int f0 = blockIdx.x * 512 + tid;
    // Block covers 512 consecutive float4 = 2 s-rows of 256.
    // Thread handles f0 (row0 1st half), f0+128 (row0 2nd half),
    // f0+256 (row1 1st half), f0+384 (row1 2nd half).

    // ---- front-batch the 4 streaming loads (MLP_p1 = 4) ----
    float4 v0 = __ldcs(&x[f0]);
    float4 v1 = __ldcs(&x[f0 + 128]);
    float4 v2 = __ldcs(&x[f0 + 256]);
    float4 v3 = __ldcs(&x[f0 + 384]);

    // ---- positions for the 2 consecutive s-rows (same b, same cols) ----
    unsigned row0 = blockIdx.x * 2;
    unsigned s = row0 & ((1u << S_LOG2) - 1u);
    unsigned b = row0 >> S_LOG2;
    unsigned cols = (unsigned)__ldg(&grid_sizes[2 * b + 1]);

    unsigned i = s / cols;                 // one division for both rows
    unsigned j = s - i * cols;
    int pos0 = (int)(i + j);
    int pos1 = (j + 1u < cols) ? pos0 + 1 : (int)(i + 1u);

    // theta_k = 10000^(-k/32) = exp2(-k * log2(10000)/32)
    int t = tid & (F4_PER_ROW - 1);        // pairs k=2t, 2t+1
    const float C = 13.287712379549449f / 32.0f;   // log2(10000)/32
    const float R = 0.7498942093324559f;           // 10000^(-1/32)
    float th0 = exp2f(-(float)(2 * t) * C);
    float th1 = th0 * R;

    // v0,v1 belong to row0 (pos0); v2,v3 belong to row1 (pos1).
    float c00, s00, c01, s01, c10, s10, c11, s11;
    __sincosf((float)pos0 * th0, &s00, &c00);
    __sincosf((float)pos0 * th1, &s01, &c01);
    __sincosf((float)pos1 * th0, &s10, &c10);
    __sincosf((float)pos1 * th1, &s11, &c11);

    float4 o0, o1, o2, o3;
    o0.x = fmaf(v0.x, c00, -v0.y * s00);
    o0.y = fmaf(v0.y, c00,  v0.x * s00);
    o0.z = fmaf(v0.z, c01, -v0.w * s01);
    o0.w = fmaf(v0.w, c01,  v0.z * s01);

    o1.x = fmaf(v1.x, c00, -v1.y * s00);
    o1.y = fmaf(v1.y, c00,  v1.x * s00);
    o1.z = fmaf(v1.z, c01, -v1.w * s01);
    o1.w = fmaf(v1.w, c01,  v1.z * s01);

    o2.x = fmaf(v2.x, c10, -v2.y * s10);
    o2.y = fmaf(v2.y, c10,  v2.x * s10);
    o2.z = fmaf(v2.z, c11, -v2.w * s11);
    o2.w = fmaf(v2.w, c11,  v2.z * s11);

    o3.x = fmaf(v3.x, c10, -v3.y * s10);
    o3.y = fmaf(v3.y, c10,  v3.x * s10);
    o3.z = fmaf(v3.z, c11, -v3.w * s11);
    o3.w = fmaf(v3.w, c11,  v3.z * s11);

    // default write-back stores (land in L2; lazy DRAM write-back)
    out[f0]       = o0;
    out[f0 + 128] = o1;
    out[f0 + 256] = o2;
    out[f0 + 384] = o3;
}

extern "C" void kernel_launch(void* const* d_in, const int* in_sizes, int n_in,
                              void* d_out, int out_size) {
    const float4* x = (const float4*)d_in[0];
    const int* grid_sizes = (const int*)d_in[1];
    float4* out = (float4*)d_out;

    int total4 = in_sizes[0] / 4;            // 8,388,608 float4
    int nblocks = total4 / 512;              // 16384 blocks of 128 threads
    rope2d_kernel<<<nblocks, 128>>>(x, grid_sizes, out);
}

// round 11
// speedup vs baseline: 1.0360x; 1.0360x over previous
#include <cuda_runtime.h>
#include <math.h>

// RoPE-2D: x[B=32, S=1024, H=16, D=64] fp32, grid_sizes[B,2] int32.
// Combined rotation: rot(i*th) ∘ rot(j*th) == rot((i+j)*th)  -> one
// {cos,sin} pair per rotation pair instead of two gathers + 8 FMAs.
//
// FINAL (proven-best, R7): one-shot grid, block=128, 4 float4/thread,
// loads front-batched with __ldcs, stores __stcs (evict-first — measured
// better than .wb, which steals L2 fill slots from the read stream).
// Per-thread fast-math sincos is fully hidden under DRAM latency.
// Kernel runs at ~95% of HBM spec on its mandatory 268 MB of traffic.

#define F4_PER_ROW 16        // D=64 floats = 16 float4
#define S_LOG2 10

__global__ void __launch_bounds__(128) rope2d_kernel(const float4* __restrict__ x,
                                                     const int* __restrict__ grid_sizes,
                                                     float4* __restrict__ out) {
    int tid = threadIdx.x;                 // 0..127
    int f0 = blockIdx.x * 512 + tid;
    // Block covers 512 consecutive float4 = 2 s-rows of 256.
    // Thread handles f0 (row0 1st half), f0+128 (row0 2nd half),
    // f0+256 (row1 1st half), f0+384 (row1 2nd half).

    // ---- front-batch the 4 streaming loads (MLP_p1 = 4) ----
    float4 v0 = __ldcs(&x[f0]);
    float4 v1 = __ldcs(&x[f0 + 128]);
    float4 v2 = __ldcs(&x[f0 + 256]);
    float4 v3 = __ldcs(&x[f0 + 384]);

    // ---- positions for the 2 consecutive s-rows (same b, same cols) ----
    unsigned row0 = blockIdx.x * 2;
    unsigned s = row0 & ((1u << S_LOG2) - 1u);
    unsigned b = row0 >> S_LOG2;
    unsigned cols = (unsigned)__ldg(&grid_sizes[2 * b + 1]);

    unsigned i = s / cols;                 // one division for both rows
    unsigned j = s - i * cols;
    int pos0 = (int)(i + j);
    int pos1 = (j + 1u < cols) ? pos0 + 1 : (int)(i + 1u);

    // theta_k = 10000^(-k/32) = exp2(-k * log2(10000)/32)
    int t = tid & (F4_PER_ROW - 1);        // pairs k=2t, 2t+1
    const float C = 13.287712379549449f / 32.0f;   // log2(10000)/32
    const float R = 0.7498942093324559f;           // 10000^(-1/32)
    float th0 = exp2f(-(float)(2 * t) * C);
    float th1 = th0 * R;

    // v0,v1 belong to row0 (pos0); v2,v3 belong to row1 (pos1).
    float c00, s00, c01, s01, c10, s10, c11, s11;
    __sincosf((float)pos0 * th0, &s00, &c00);
    __sincosf((float)pos0 * th1, &s01, &c01);
    __sincosf((float)pos1 * th0, &s10, &c10);
    __sincosf((float)pos1 * th1, &s11, &c11);

    float4 o0, o1, o2, o3;
    o0.x = fmaf(v0.x, c00, -v0.y * s00);
    o0.y = fmaf(v0.y, c00,  v0.x * s00);
    o0.z = fmaf(v0.z, c01, -v0.w * s01);
    o0.w = fmaf(v0.w, c01,  v0.z * s01);

    o1.x = fmaf(v1.x, c00, -v1.y * s00);
    o1.y = fmaf(v1.y, c00,  v1.x * s00);
    o1.z = fmaf(v1.z, c01, -v1.w * s01);
    o1.w = fmaf(v1.w, c01,  v1.z * s01);

    o2.x = fmaf(v2.x, c10, -v2.y * s10);
    o2.y = fmaf(v2.y, c10,  v2.x * s10);
    o2.z = fmaf(v2.z, c11, -v2.w * s11);
    o2.w = fmaf(v2.w, c11,  v2.z * s11);

    o3.x = fmaf(v3.x, c10, -v3.y * s10);
    o3.y = fmaf(v3.y, c10,  v3.x * s10);
    o3.z = fmaf(v3.z, c11, -v3.w * s11);
    o3.w = fmaf(v3.w, c11,  v3.z * s11);

    __stcs(&out[f0],       o0);
    __stcs(&out[f0 + 128], o1);
    __stcs(&out[f0 + 256], o2);
    __stcs(&out[f0 + 384], o3);
}

extern "C" void kernel_launch(void* const* d_in, const int* in_sizes, int n_in,
                              void* d_out, int out_size) {
    const float4* x = (const float4*)d_in[0];
    const int* grid_sizes = (const int*)d_in[1];
    float4* out = (float4*)d_out;

    int total4 = in_sizes[0] / 4;            // 8,388,608 float4
    int nblocks = total4 / 512;              // 16384 blocks of 128 threads
    rope2d_kernel<<<nblocks, 128>>>(x, grid_sizes, out);
}

// round 12
// speedup vs baseline: 1.0368x; 1.0007x over previous
#include <cuda_runtime.h>
#include <math.h>

// RoPE-2D: x[B=32, S=1024, H=16, D=64] fp32, grid_sizes[B,2] int32.
// Combined rotation: rot(i*th) ∘ rot(j*th) == rot((i+j)*th)  -> one
// {cos,sin} pair per rotation pair instead of two gathers + 8 FMAs.
//
// Config: one-shot grid, block=64, 4 float4/thread, ONE s-row per block
// (all 4 vectors share one pos -> 2 sincos/thread, no row-wrap logic).
// Loads front-batched with __ldcs; stores __stcs (evict-first, measured
// better than .wb). Finest CTA tail quantum (2-warp CTAs).

#define F4_PER_ROW 16        // D=64 floats = 16 float4
#define S_LOG2 10

__global__ void __launch_bounds__(64) rope2d_kernel(const float4* __restrict__ x,
                                                    const int* __restrict__ grid_sizes,
                                                    float4* __restrict__ out) {
    int tid = threadIdx.x;                 // 0..63
    int f0 = blockIdx.x * 256 + tid;
    // Block covers one s-row = 256 float4. Thread handles
    // f0, f0+64, f0+128, f0+192 (4 heads' worth, same (b,s), same t).

    // ---- front-batch the 4 streaming loads (MLP_p1 = 4) ----
    float4 v0 = __ldcs(&x[f0]);
    float4 v1 = __ldcs(&x[f0 + 64]);
    float4 v2 = __ldcs(&x[f0 + 128]);
    float4 v3 = __ldcs(&x[f0 + 192]);

    // ---- position for this row ----
    unsigned row = blockIdx.x;
    unsigned s = row & ((1u << S_LOG2) - 1u);
    unsigned b = row >> S_LOG2;
    unsigned cols = (unsigned)__ldg(&grid_sizes[2 * b + 1]);
    unsigned i = s / cols;
    unsigned j = s - i * cols;
    int pos = (int)(i + j);

    // theta_k = 10000^(-k/32) = exp2(-k * log2(10000)/32)
    int t = tid & (F4_PER_ROW - 1);        // pairs k=2t, 2t+1
    const float C = 13.287712379549449f / 32.0f;   // log2(10000)/32
    const float R = 0.7498942093324559f;           // 10000^(-1/32)
    float th0 = exp2f(-(float)(2 * t) * C);
    float th1 = th0 * R;

    float ca, sa, cb, sb;
    __sincosf((float)pos * th0, &sa, &ca);
    __sincosf((float)pos * th1, &sb, &cb);

    float4 o0, o1, o2, o3;
    o0.x = fmaf(v0.x, ca, -v0.y * sa);
    o0.y = fmaf(v0.y, ca,  v0.x * sa);
    o0.z = fmaf(v0.z, cb, -v0.w * sb);
    o0.w = fmaf(v0.w, cb,  v0.z * sb);

    o1.x = fmaf(v1.x, ca, -v1.y * sa);
    o1.y = fmaf(v1.y, ca,  v1.x * sa);
    o1.z = fmaf(v1.z, cb, -v1.w * sb);
    o1.w = fmaf(v1.w, cb,  v1.z * sb);

    o2.x = fmaf(v2.x, ca, -v2.y * sa);
    o2.y = fmaf(v2.y, ca,  v2.x * sa);
    o2.z = fmaf(v2.z, cb, -v2.w * sb);
    o2.w = fmaf(v2.w, cb,  v2.z * sb);

    o3.x = fmaf(v3.x, ca, -v3.y * sa);
    o3.y = fmaf(v3.y, ca,  v3.x * sa);
    o3.z = fmaf(v3.z, cb, -v3.w * sb);
    o3.w = fmaf(v3.w, cb,  v3.z * sb);

    __stcs(&out[f0],       o0);
    __stcs(&out[f0 + 64],  o1);
    __stcs(&out[f0 + 128], o2);
    __stcs(&out[f0 + 192], o3);
}

extern "C" void kernel_launch(void* const* d_in, const int* in_sizes, int n_in,
                              void* d_out, int out_size) {
    const float4* x = (const float4*)d_in[0];
    const int* grid_sizes = (const int*)d_in[1];
    float4* out = (float4*)d_out;

    int total4 = in_sizes[0] / 4;            // 8,388,608 float4
    int nblocks = total4 / 256;              // 32768 blocks of 64 threads
    rope2d_kernel<<<nblocks, 64>>>(x, grid_sizes, out);
}